// round 5
// baseline (speedup 1.0000x reference)
#include <cuda_runtime.h>

#define PATCHES  196
#define FEATS    784
#define CLASSES  10

typedef unsigned long long u64;

// ---- packed f32x2 helpers (Blackwell sm_103a) ----
__device__ __forceinline__ u64 pk2(float lo, float hi) {
    u64 d;
    asm("mov.b64 %0, {%1, %2};"
        : "=l"(d) : "r"(__float_as_uint(lo)), "r"(__float_as_uint(hi)));
    return d;
}
__device__ __forceinline__ void upk2(u64 v, float& lo, float& hi) {
    unsigned a, b;
    asm("mov.b64 {%0, %1}, %2;" : "=r"(a), "=r"(b) : "l"(v));
    lo = __uint_as_float(a); hi = __uint_as_float(b);
}
__device__ __forceinline__ u64 f2mul(u64 a, u64 b) {
    u64 d; asm("mul.rn.f32x2 %0, %1, %2;" : "=l"(d) : "l"(a), "l"(b)); return d;
}
__device__ __forceinline__ u64 f2fma(u64 a, u64 b, u64 c) {
    u64 d; asm("fma.rn.f32x2 %0, %1, %2, %3;" : "=l"(d) : "l"(a), "l"(b), "l"(c)); return d;
}

// RX rotation on packed amplitude pair (i,j):
//   a_i' = c a_i - i s a_j ; a_j' = c a_j - i s a_i   (both substates at once)
#define RX_PAIR(i, j, C, S, NS)                      \
    do {                                             \
        u64 r0 = R[i], i0 = I[i], r1 = R[j], i1 = I[j]; \
        R[i] = f2fma(C, r0, f2mul(S,  i1));          \
        I[i] = f2fma(C, i0, f2mul(NS, r1));          \
        R[j] = f2fma(C, r1, f2mul(S,  i0));          \
        I[j] = f2fma(C, i1, f2mul(NS, r0));          \
    } while (0)

__global__ __launch_bounds__(256)
void quanv_fused_kernel(const float* __restrict__ x,    // [1024,1,28,28]
                        const float* __restrict__ qp,   // [3,4]
                        const float* __restrict__ W,    // [10,784]
                        const float* __restrict__ bias, // [10]
                        float* __restrict__ out)        // [1024,10]
{
    __shared__ float feats[FEATS];
    __shared__ float s_logits[CLASSES];
    // RZ phase factors, packed over substates: entry e = l*4 + i  (l=layer 0..1, i=amp)
    __shared__ u64 s_PR[8], s_PI[8], s_NPI[8];

    const int bidx = blockIdx.x;
    const int tid  = threadIdx.x;

    if (tid < 8) {
        int l = tid >> 2, i = tid & 3;
        // substate 0 -> wires (0,1); substate 1 -> wires (2,3)
        float qh0 = qp[l * 4 + 0], ql0 = qp[l * 4 + 1];
        float qh1 = qp[l * 4 + 2], ql1 = qp[l * 4 + 3];
        float th0 = 0.5f * (((i & 2) ? qh0 : -qh0) + ((i & 1) ? ql0 : -ql0));
        float th1 = 0.5f * (((i & 2) ? qh1 : -qh1) + ((i & 1) ? ql1 : -ql1));
        float s0, c0, s1, c1;
        __sincosf(th0, &s0, &c0);
        __sincosf(th1, &s1, &c1);
        s_PR[tid]  = pk2(c0, c1);
        s_PI[tid]  = pk2(s0, s1);
        s_NPI[tid] = pk2(-s0, -s1);
    }
    __syncthreads();

    if (tid < PATCHES) {
        const int r = tid / 14, c = tid % 14;
        const float* xb = x + (size_t)bidx * 784;
        float2 top = *(const float2*)(xb + (2 * r) * 28 + 2 * c);
        float2 bot = *(const float2*)(xb + (2 * r + 1) * 28 + 2 * c);
        float ang[4] = {top.x, top.y, bot.x, bot.y};

        float cs[4], sn[4];
#pragma unroll
        for (int w = 0; w < 4; w++)
            __sincosf(ang[w] * 0.5f, &sn[w], &cs[w]);

        // Pack both substates lane-wise: lo half = substate 0, hi half = substate 1.
        const u64 CH  = pk2(cs[0], cs[2]);
        const u64 SH  = pk2(sn[0], sn[2]);
        const u64 NSH = pk2(-sn[0], -sn[2]);
        const u64 CL  = pk2(cs[1], cs[3]);
        const u64 SL  = pk2(sn[1], sn[3]);
        const u64 NSL = pk2(-sn[1], -sn[3]);

        // --- layer 0 on |00>, closed form, with CNOT(hi->lo) already folded ---
        //  re0 = ch*cl ; im1 = -ch*sl ; re2 = -sh*sl ; im3 = -sh*cl
        u64 R[4], I[4];
        R[0] = f2mul(CH, CL);   I[0] = 0ull;
        R[1] = 0ull;            I[1] = f2mul(CH, NSL);
        R[2] = f2mul(NSH, SL);  I[2] = 0ull;
        R[3] = 0ull;            I[3] = f2mul(NSH, CL);

        // --- RZ layer 0 (both wires fused per amp) ---
#pragma unroll
        for (int i = 0; i < 4; i++) {
            u64 pr = s_PR[i], pi = s_PI[i], npi = s_NPI[i];
            u64 r0 = R[i], i0 = I[i];
            R[i] = f2fma(pr, r0, f2mul(npi, i0));
            I[i] = f2fma(pr, i0, f2mul(pi,  r0));
        }

        // --- layer 1: RX both wires, CNOT, RZ ---
        RX_PAIR(0, 2, CH, SH, NSH);
        RX_PAIR(1, 3, CH, SH, NSH);
        RX_PAIR(0, 1, CL, SL, NSL);
        RX_PAIR(2, 3, CL, SL, NSL);
        { u64 t;
          t = R[2]; R[2] = R[3]; R[3] = t;
          t = I[2]; I[2] = I[3]; I[3] = t; }
#pragma unroll
        for (int i = 0; i < 4; i++) {
            u64 pr = s_PR[4 + i], pi = s_PI[4 + i], npi = s_NPI[4 + i];
            u64 r0 = R[i], i0 = I[i];
            R[i] = f2fma(pr, r0, f2mul(npi, i0));
            I[i] = f2fma(pr, i0, f2mul(pi,  r0));
        }

        // --- layer 2: RX both wires. Final CNOT folded into z_lo remap;
        //     final RZ is a dead phase under |.|^2. ---
        RX_PAIR(0, 2, CH, SH, NSH);
        RX_PAIR(1, 3, CH, SH, NSH);
        RX_PAIR(0, 1, CL, SL, NSL);
        RX_PAIR(2, 3, CL, SL, NSL);

        // packed probabilities, then unpack
        float p[2][4];
#pragma unroll
        for (int i = 0; i < 4; i++) {
            u64 P = f2fma(R[i], R[i], f2mul(I[i], I[i]));
            upk2(P, p[0][i], p[1][i]);
        }
#pragma unroll
        for (int s = 0; s < 2; s++) {
            // CNOT would swap p2<->p3: z_hi invariant, z_lo uses swapped pair.
            float z_hi = (p[s][0] + p[s][1]) - (p[s][2] + p[s][3]);
            float z_lo = (p[s][0] + p[s][3]) - (p[s][1] + p[s][2]);
            feats[tid * 4 + 2 * s]     = z_hi;
            feats[tid * 4 + 2 * s + 1] = z_lo;
        }
    }
    __syncthreads();

    // Logits: 8 warps; warp wp covers classes {wp, wp+8}
    const int wp = tid >> 5, lane = tid & 31;
    for (int cls = wp; cls < CLASSES; cls += 8) {
        float acc = 0.f;
        const float* Wc = W + cls * FEATS;
#pragma unroll 4
        for (int i = lane; i < FEATS; i += 32)
            acc = fmaf(feats[i], Wc[i], acc);
#pragma unroll
        for (int off = 16; off > 0; off >>= 1)
            acc += __shfl_down_sync(0xffffffffu, acc, off);
        if (lane == 0) s_logits[cls] = acc + bias[cls];
    }
    __syncthreads();

    // Warp 0: parallel log_softmax over 10 logits, write output directly.
    if (wp == 0) {
        float v = (lane < CLASSES) ? s_logits[lane] : -3.4e38f;
        float m = v;
#pragma unroll
        for (int off = 16; off > 0; off >>= 1)
            m = fmaxf(m, __shfl_xor_sync(0xffffffffu, m, off));
        float e = (lane < CLASSES) ? __expf(v - m) : 0.f;
        float sum = e;
#pragma unroll
        for (int off = 16; off > 0; off >>= 1)
            sum += __shfl_xor_sync(0xffffffffu, sum, off);
        float lse = m + __logf(sum);
        if (lane < CLASSES)
            out[(size_t)bidx * CLASSES + lane] = v - lse;
    }
}

extern "C" void kernel_launch(void* const* d_in, const int* in_sizes, int n_in,
                              void* d_out, int out_size) {
    const float* x  = (const float*)d_in[0];   // [1024,1,28,28]
    const float* qp = (const float*)d_in[1];   // [3,4]
    const float* W  = (const float*)d_in[2];   // [10,784]
    const float* b  = (const float*)d_in[3];   // [10]
    float* out = (float*)d_out;                // [1024,10]
    quanv_fused_kernel<<<1024, 256>>>(x, qp, W, b, out);
}

// round 7
// speedup vs baseline: 1.2179x; 1.2179x over previous
#include <cuda_runtime.h>

#define PATCHES  196
#define FEATS    784
#define CLASSES  10

// RX rotation on an amplitude pair: a_i' = c a_i - i s a_j ; a_j' = c a_j - i s a_i
__device__ __forceinline__ void rx_pair(float* re, float* im, int i, int j,
                                        float c, float s) {
    float r0 = re[i], i0 = im[i], r1 = re[j], i1 = im[j];
    re[i] = fmaf(c, r0,  s * i1);
    im[i] = fmaf(c, i0, -s * r1);
    re[j] = fmaf(c, r1,  s * i0);
    im[j] = fmaf(c, i1, -s * r0);
}

__global__ __launch_bounds__(224)
void quanv_fused_kernel(const float* __restrict__ x,    // [1024,1,28,28]
                        const float* __restrict__ qp,   // [3,4]
                        const float* __restrict__ W,    // [10,784]
                        const float* __restrict__ bias, // [10]
                        float* __restrict__ out)        // [1024,10]
{
    __shared__ __align__(16) float feats[FEATS];
    __shared__ float s_logits[CLASSES];
    // Layer-0 combo: RZ(phase) applied to the purely-real/imag closed-form state,
    // signs prefolded. index = s*4 + i  -> multiply by {chcl, chsl, shsl, shcl}[i]
    __shared__ float s_c0r[8], s_c0i[8];
    // Layer-1 RZ phase factors (plain complex). index = s*4 + i
    __shared__ float s_p1r[8], s_p1i[8];

    const int bidx = blockIdx.x;
    const int tid  = threadIdx.x;

    if (tid < 8) {
        int s = tid >> 2, i = tid & 3;
        // layer 0
        {
            float qh = qp[2 * s], ql = qp[2 * s + 1];
            float th = 0.5f * (((i & 2) ? qh : -qh) + ((i & 1) ? ql : -ql));
            float pr, pi;
            __sincosf(th, &pi, &pr);
            // amp0: (pr, pi); amp1/amp3: (pi, -pr); amp2: (-pr, -pi)
            float cr, ci;
            if (i == 0)      { cr =  pr; ci =  pi; }
            else if (i == 2) { cr = -pr; ci = -pi; }
            else             { cr =  pi; ci = -pr; }
            s_c0r[tid] = cr; s_c0i[tid] = ci;
        }
        // layer 1
        {
            float qh = qp[4 + 2 * s], ql = qp[4 + 2 * s + 1];
            float th = 0.5f * (((i & 2) ? qh : -qh) + ((i & 1) ? ql : -ql));
            __sincosf(th, &s_p1i[tid], &s_p1r[tid]);
        }
    }
    __syncthreads();

    if (tid < PATCHES) {
        const int r = tid / 14, c = tid % 14;
        const float* xb = x + (size_t)bidx * 784;
        float2 top = *(const float2*)(xb + (2 * r) * 28 + 2 * c);
        float2 bot = *(const float2*)(xb + (2 * r + 1) * 28 + 2 * c);
        float ang[4] = {top.x, top.y, bot.x, bot.y};

        float cs[4], sn[4];
#pragma unroll
        for (int w = 0; w < 4; w++)
            __sincosf(ang[w] * 0.5f, &sn[w], &cs[w]);

        // Two independent 2-qubit substates: s=0 -> wires(0,1), s=1 -> wires(2,3)
#pragma unroll
        for (int s = 0; s < 2; s++) {
            const float ch = cs[2 * s],     sh = sn[2 * s];
            const float cl = cs[2 * s + 1], sl = sn[2 * s + 1];

            // --- layer 0 (RX closed form on |00>) + CNOT + RZ0, all folded:
            //     each amp is mag[i] * (s_c0r[i] + i s_c0i[i]) ---
            const float chcl = ch * cl, chsl = ch * sl;
            const float shsl = sh * sl, shcl = sh * cl;
            float re[4], im[4];
            re[0] = chcl * s_c0r[s * 4 + 0];  im[0] = chcl * s_c0i[s * 4 + 0];
            re[1] = chsl * s_c0r[s * 4 + 1];  im[1] = chsl * s_c0i[s * 4 + 1];
            re[2] = shsl * s_c0r[s * 4 + 2];  im[2] = shsl * s_c0i[s * 4 + 2];
            re[3] = shcl * s_c0r[s * 4 + 3];  im[3] = shcl * s_c0i[s * 4 + 3];

            // --- layer 1: RX both wires, CNOT, RZ ---
            rx_pair(re, im, 0, 2, ch, sh);
            rx_pair(re, im, 1, 3, ch, sh);
            rx_pair(re, im, 0, 1, cl, sl);
            rx_pair(re, im, 2, 3, cl, sl);
            { float t;
              t = re[2]; re[2] = re[3]; re[3] = t;
              t = im[2]; im[2] = im[3]; im[3] = t; }
#pragma unroll
            for (int i = 0; i < 4; i++) {
                float pr = s_p1r[s * 4 + i], pi = s_p1i[s * 4 + i];
                float r0 = re[i], i0 = im[i];
                re[i] = fmaf(pr, r0, -pi * i0);
                im[i] = fmaf(pr, i0,  pi * r0);
            }

            // --- layer 2: RX both wires. Final CNOT folded into z_lo remap;
            //     final RZ is a dead phase under |.|^2. ---
            rx_pair(re, im, 0, 2, ch, sh);
            rx_pair(re, im, 1, 3, ch, sh);
            rx_pair(re, im, 0, 1, cl, sl);
            rx_pair(re, im, 2, 3, cl, sl);

            float p0 = fmaf(re[0], re[0], im[0] * im[0]);
            float p1 = fmaf(re[1], re[1], im[1] * im[1]);
            float p2 = fmaf(re[2], re[2], im[2] * im[2]);
            float p3 = fmaf(re[3], re[3], im[3] * im[3]);
            // CNOT would swap p2<->p3: z_hi invariant, z_lo uses swapped pair.
            float z_hi = (p0 + p1) - (p2 + p3);
            float z_lo = (p0 + p3) - (p1 + p2);
            feats[tid * 4 + 2 * s]     = z_hi;
            feats[tid * 4 + 2 * s + 1] = z_lo;
        }
    }
    __syncthreads();

    // Logits: 7 warps; warp wp covers classes {wp, wp+7}. float4 everywhere:
    // 196 float4 per class = 6 full warp iterations + 4-lane remainder.
    const int wp = tid >> 5, lane = tid & 31;
    const float4* Fv = (const float4*)feats;
    for (int cls = wp; cls < CLASSES; cls += 7) {
        const float4* Wv = (const float4*)(W + cls * FEATS);
        float acc = 0.f;
#pragma unroll
        for (int k = 0; k < 6; k++) {
            float4 f = Fv[lane + 32 * k];
            float4 w = Wv[lane + 32 * k];
            acc = fmaf(f.x, w.x, acc);
            acc = fmaf(f.y, w.y, acc);
            acc = fmaf(f.z, w.z, acc);
            acc = fmaf(f.w, w.w, acc);
        }
        if (lane < 4) {
            float4 f = Fv[192 + lane];
            float4 w = Wv[192 + lane];
            acc = fmaf(f.x, w.x, acc);
            acc = fmaf(f.y, w.y, acc);
            acc = fmaf(f.z, w.z, acc);
            acc = fmaf(f.w, w.w, acc);
        }
#pragma unroll
        for (int off = 16; off > 0; off >>= 1)
            acc += __shfl_down_sync(0xffffffffu, acc, off);
        if (lane == 0) s_logits[cls] = acc + bias[cls];
    }
    __syncthreads();

    // Warp 0: parallel log_softmax over 10 logits, write output directly.
    if (wp == 0) {
        float v = (lane < CLASSES) ? s_logits[lane] : -3.4e38f;
        float m = v;
#pragma unroll
        for (int off = 16; off > 0; off >>= 1)
            m = fmaxf(m, __shfl_xor_sync(0xffffffffu, m, off));
        float e = (lane < CLASSES) ? __expf(v - m) : 0.f;
        float sum = e;
#pragma unroll
        for (int off = 16; off > 0; off >>= 1)
            sum += __shfl_xor_sync(0xffffffffu, sum, off);
        float lse = m + __logf(sum);
        if (lane < CLASSES)
            out[(size_t)bidx * CLASSES + lane] = v - lse;
    }
}

extern "C" void kernel_launch(void* const* d_in, const int* in_sizes, int n_in,
                              void* d_out, int out_size) {
    const float* x  = (const float*)d_in[0];   // [1024,1,28,28]
    const float* qp = (const float*)d_in[1];   // [3,4]
    const float* W  = (const float*)d_in[2];   // [10,784]
    const float* b  = (const float*)d_in[3];   // [10]
    float* out = (float*)d_out;                // [1024,10]
    quanv_fused_kernel<<<1024, 224>>>(x, qp, W, b, out);
}